// round 5
// baseline (speedup 1.0000x reference)
#include <cuda_runtime.h>
#include <math.h>

#define NMAX 50000
#define EMAX 640000
#define ETOTMAX (EMAX + NMAX)
#define DH 128
#define DOUT 16
#define NG 64

typedef unsigned long long ull;

// scratch (device globals; zero-initialized at module load)
__device__ float g_h1[NMAX * DH];
__device__ float g_out1[NMAX * DH];
__device__ float g_h2[NMAX * DOUT];
__device__ float g_out2[NMAX * DOUT];
__device__ float g_als1[NMAX], g_ald1[NMAX];
__device__ float g_als2[NMAX], g_ald2[NMAX];
__device__ int   g_deg[NMAX];          // zeroed by k_scatter for next call
__device__ int   g_rowptr[NMAX + 1];
__device__ int   g_cursor[NMAX];
__device__ int   g_srcs[ETOTMAX];
__device__ float g_pooled[NG * DOUT];  // zeroed by k_final for next call
__device__ float g_cnt[NG];

// ---- packed fp32x2 helpers (Blackwell FFMA2) --------------------------------
__device__ __forceinline__ ull pk2(float lo, float hi) {
    ull r; asm("mov.b64 %0, {%1, %2};" : "=l"(r) : "f"(lo), "f"(hi)); return r;
}
__device__ __forceinline__ void upk2(ull v, float& lo, float& hi) {
    asm("mov.b64 {%0, %1}, %2;" : "=f"(lo), "=f"(hi) : "l"(v));
}
__device__ __forceinline__ void fma2(ull& d, ull a, ull b) {
    asm("fma.rn.f32x2 %0, %1, %2, %3;" : "=l"(d) : "l"(a), "l"(b), "l"(d));
}

// ---------------------------------------------------------------------------
// histogram of edge destination degrees (self loops handled algebraically)
__global__ void k_hist(const int* __restrict__ ei, int E) {
    int i = blockIdx.x * blockDim.x + threadIdx.x;
    int E4 = E >> 2;
    if (i < E4) {
        int4 d = ((const int4*)(ei + E))[i];
        atomicAdd(&g_deg[d.x], 1);
        atomicAdd(&g_deg[d.y], 1);
        atomicAdd(&g_deg[d.z], 1);
        atomicAdd(&g_deg[d.w], 1);
    } else if (i == E4) {
        for (int j = E4 * 4; j < E; j++) atomicAdd(&g_deg[ei[E + j]], 1);
    }
}

// single-block scan: per-thread serial chunk + 2-level shuffle scan.
// rowptr[i] = prefix(deg[i] + 1)   (the +1 is the self loop)
__global__ void __launch_bounds__(1024) k_scan(int M) {
    __shared__ int warpsum[32];
    int t = threadIdx.x;
    int C = (M + 1023) >> 10;
    int lo = t * C, hi = min(lo + C, M);
    if (lo > M) lo = M;
    if (hi < lo) hi = lo;
    int s = 0;
    for (int i = lo; i < hi; i++) s += g_deg[i] + 1;
    int lane = t & 31, w = t >> 5;
    int v = s;
#pragma unroll
    for (int o = 1; o < 32; o <<= 1) {
        int u = __shfl_up_sync(0xffffffffu, v, o);
        if (lane >= o) v += u;
    }
    if (lane == 31) warpsum[w] = v;
    __syncthreads();
    if (w == 0) {
        int u = warpsum[lane];
#pragma unroll
        for (int o = 1; o < 32; o <<= 1) {
            int z = __shfl_up_sync(0xffffffffu, u, o);
            if (lane >= o) u += z;
        }
        warpsum[lane] = u;
    }
    __syncthreads();
    int excl = v - s + (w ? warpsum[w - 1] : 0);
    int run = excl;
    for (int i = lo; i < hi; i++) {
        g_rowptr[i] = run;
        g_cursor[i] = run;
        run += g_deg[i] + 1;
    }
    if (t == 1023) g_rowptr[M] = run;
}

// scatter srcs into CSR slots; self-loop threads also zero g_deg for next call
__global__ void k_scatter(const int* __restrict__ ei, int E, int M) {
    int i = blockIdx.x * blockDim.x + threadIdx.x;
    int E4 = E >> 2;
    if (i < E4) {
        int4 s4 = ((const int4*)ei)[i];
        int4 d4 = ((const int4*)(ei + E))[i];
        int p;
        p = atomicAdd(&g_cursor[d4.x], 1); g_srcs[p] = s4.x;
        p = atomicAdd(&g_cursor[d4.y], 1); g_srcs[p] = s4.y;
        p = atomicAdd(&g_cursor[d4.z], 1); g_srcs[p] = s4.z;
        p = atomicAdd(&g_cursor[d4.w], 1); g_srcs[p] = s4.w;
    } else if (i == E4) {
        for (int j = E4 * 4; j < E; j++) {
            int p = atomicAdd(&g_cursor[ei[E + j]], 1);
            g_srcs[p] = ei[j];
        }
    } else {
        int j = i - E4 - 1;
        if (j < M) {
            int p = atomicAdd(&g_cursor[j], 1);
            g_srcs[p] = j;
            g_deg[j] = 0;   // reset for next call (scan already consumed it)
        }
    }
}

// ---------------------------------------------------------------------------
// GEMM1: h1[M,128] = x @ W1, packed f32x2, 64-row tile, 2 rows/thread.
// W staged ONCE into 64KB smem; x tile register-staged double-buffered
// (one __syncthreads per 32-k chunk; LDG for chunk kc+1 overlaps compute of kc).
// dyn smem: Wp [128][64 pairs] (65536B) | xb [2][32][XP pairs]
#define XP 65
#define XBUF_PAIRS (32 * XP)
#define SMEM1_BYTES (65536 + 2 * XBUF_PAIRS * 8)

extern "C" __global__ void __launch_bounds__(256) k_gemm1(
    const float* __restrict__ x, const float* __restrict__ W,
    const float* __restrict__ as, const float* __restrict__ ad, int M)
{
    extern __shared__ char dynsmem[];
    ull*    Wp  = (ull*)dynsmem;                 // [128 k][64 pairs]
    float2* xb  = (float2*)(dynsmem + 65536);    // [2][32 k][XP] duplicated pairs
    float*  red = (float*)(dynsmem + 65536);     // reused post-loop [2][8][64]

    int tid  = threadIdx.x;
    int lane = tid & 31;
    int wid  = tid >> 5;
    int rb   = blockIdx.x * 64;

    // stage ALL of W (4096 float4 = 64KB), once
    for (int t = tid; t < 4096; t += 256)
        ((float4*)Wp)[t] = ((const float4*)W)[t];

    // this thread's two x-load slots: t = tid + q*256 -> (r = t>>3, kq = t&7)
    int r0 = tid >> 3, kq0 = tid & 7;
    int r1 = (tid + 256) >> 3, kq1 = (tid + 256) & 7;
    const float4 z4 = make_float4(0.f, 0.f, 0.f, 0.f);

    // prefetch chunk 0
    float4 pf0, pf1;
    {
        int row0 = rb + r0, row1 = rb + r1;
        pf0 = (row0 < M) ? ((const float4*)(x + (size_t)row0 * DH))[kq0] : z4;
        pf1 = (row1 < M) ? ((const float4*)(x + (size_t)row1 * DH))[kq1] : z4;
    }

    ull acc2[2][8];
#pragma unroll
    for (int i = 0; i < 2; i++)
#pragma unroll
        for (int j = 0; j < 8; j++) acc2[i][j] = 0ull;

    for (int kc = 0; kc < 4; kc++) {
        // store prefetched tile into buffer kc&1 (duplicated pairs, transposed)
        float2* xc = xb + (kc & 1) * XBUF_PAIRS;
        xc[(kq0 * 4 + 0) * XP + r0] = make_float2(pf0.x, pf0.x);
        xc[(kq0 * 4 + 1) * XP + r0] = make_float2(pf0.y, pf0.y);
        xc[(kq0 * 4 + 2) * XP + r0] = make_float2(pf0.z, pf0.z);
        xc[(kq0 * 4 + 3) * XP + r0] = make_float2(pf0.w, pf0.w);
        xc[(kq1 * 4 + 0) * XP + r1] = make_float2(pf1.x, pf1.x);
        xc[(kq1 * 4 + 1) * XP + r1] = make_float2(pf1.y, pf1.y);
        xc[(kq1 * 4 + 2) * XP + r1] = make_float2(pf1.z, pf1.z);
        xc[(kq1 * 4 + 3) * XP + r1] = make_float2(pf1.w, pf1.w);
        __syncthreads();

        // prefetch chunk kc+1 (latency hidden behind the 32-k compute below)
        if (kc < 3) {
            int row0 = rb + r0, row1 = rb + r1;
            const float* xo = x + (size_t)(kc + 1) * 32;
            pf0 = (row0 < M) ? ((const float4*)(xo + (size_t)row0 * DH))[kq0] : z4;
            pf1 = (row1 < M) ? ((const float4*)(xo + (size_t)row1 * DH))[kq1] : z4;
        }

        const ull* Wk = Wp + (size_t)(kc * 32) * 64 + wid * 8;
#pragma unroll
        for (int k = 0; k < 32; k++) {
            const ulonglong2* Wr = (const ulonglong2*)(Wk + (size_t)k * 64);
            ulonglong2 wa = Wr[0], wb = Wr[1], wc = Wr[2], wd = Wr[3];
            ull xp0 = *(const ull*)&xc[k * XP + lane];
            ull xp1 = *(const ull*)&xc[k * XP + lane + 32];
            fma2(acc2[0][0], xp0, wa.x); fma2(acc2[0][1], xp0, wa.y);
            fma2(acc2[0][2], xp0, wb.x); fma2(acc2[0][3], xp0, wb.y);
            fma2(acc2[0][4], xp0, wc.x); fma2(acc2[0][5], xp0, wc.y);
            fma2(acc2[0][6], xp0, wd.x); fma2(acc2[0][7], xp0, wd.y);
            fma2(acc2[1][0], xp1, wa.x); fma2(acc2[1][1], xp1, wa.y);
            fma2(acc2[1][2], xp1, wb.x); fma2(acc2[1][3], xp1, wb.y);
            fma2(acc2[1][4], xp1, wc.x); fma2(acc2[1][5], xp1, wc.y);
            fma2(acc2[1][6], xp1, wd.x); fma2(acc2[1][7], xp1, wd.y);
        }
        // next iteration's STS targets the other buffer; the sync above
        // guarantees the buffer it overwrites (read in iter kc-1) is drained.
    }

    ull asl2[8], adl2[8];
#pragma unroll
    for (int j = 0; j < 8; j++) {
        asl2[j] = pk2(as[wid * 16 + 2 * j], as[wid * 16 + 2 * j + 1]);
        adl2[j] = pk2(ad[wid * 16 + 2 * j], ad[wid * 16 + 2 * j + 1]);
    }

    __syncthreads();               // xb about to be reused as reduction buffer

#pragma unroll
    for (int i = 0; i < 2; i++) {
        int r = lane + 32 * i;
        int row = rb + r;
        if (row < M) {
            ulonglong2* hp = (ulonglong2*)(g_h1 + (size_t)row * DH + wid * 16);
#pragma unroll
            for (int q = 0; q < 4; q++) {
                ulonglong2 v; v.x = acc2[i][2 * q]; v.y = acc2[i][2 * q + 1];
                hp[q] = v;
            }
        }
        ull ps2 = 0ull, pd2 = 0ull;
#pragma unroll
        for (int j = 0; j < 8; j++) {
            fma2(ps2, acc2[i][j], asl2[j]);
            fma2(pd2, acc2[i][j], adl2[j]);
        }
        float a, b, c, d;
        upk2(ps2, a, b);
        upk2(pd2, c, d);
        red[0 * 512 + wid * 64 + r] = a + b;
        red[1 * 512 + wid * 64 + r] = c + d;
    }
    __syncthreads();
    if (tid < 128) {
        int which = tid >> 6, r = tid & 63;
        float s = 0.f;
#pragma unroll
        for (int w = 0; w < 8; w++) s += red[which * 512 + w * 64 + r];
        int row = rb + r;
        if (row < M) {
            if (which == 0) g_als1[row] = s; else g_ald1[row] = s;
        }
    }
}

// ---------------------------------------------------------------------------
// agg1: one warp per dst node. Logits are bounded (|als+ald| ~< 15), so
// plain exp (no max subtraction) is safe and kills the serial softmax chain.
__global__ void __launch_bounds__(256) k_agg1(const float* __restrict__ b1, int M) {
    int warp = (blockIdx.x * blockDim.x + threadIdx.x) >> 5;
    int lane = threadIdx.x & 31;
    if (warp >= M) return;
    int s = g_rowptr[warp], e = g_rowptr[warp + 1];
    float aldv = g_ald1[warp];
    float ssum = 0.f;
    float4 acc = make_float4(0.f, 0.f, 0.f, 0.f);
#pragma unroll 4
    for (int i = s; i < e; i++) {
        int u = g_srcs[i];
        float logit = g_als1[u] + aldv;
        logit = (logit > 0.f) ? logit : 0.2f * logit;
        float p = __expf(logit);
        const float4 hv = ((const float4*)(g_h1 + (size_t)u * DH))[lane];
        ssum += p;
        acc.x += p * hv.x;
        acc.y += p * hv.y;
        acc.z += p * hv.z;
        acc.w += p * hv.w;
    }
    float inv = 1.f / ssum;
    float4 bv = ((const float4*)b1)[lane];
    float4 o;
    o.x = fmaxf(acc.x * inv + bv.x, 0.f);
    o.y = fmaxf(acc.y * inv + bv.y, 0.f);
    o.z = fmaxf(acc.z * inv + bv.z, 0.f);
    o.w = fmaxf(acc.w * inv + bv.w, 0.f);
    ((float4*)(g_out1 + (size_t)warp * DH))[lane] = o;
}

// ---------------------------------------------------------------------------
// GEMM2: h2[M,16] = out1 @ W2, packed f32x2. 128 threads / 32-row tile.
__global__ void __launch_bounds__(128) k_gemm2(
    const float* __restrict__ W2, const float* __restrict__ as,
    const float* __restrict__ ad, int M)
{
    __shared__ ull   W2s[DH * 8];        // [k][8 pairs]
    __shared__ float xs[32 * 133];       // [r][k], pitch 133
    __shared__ float sred[2][32][4];

    int tid = threadIdx.x;
    int lane = tid & 31;
    int w = tid >> 5;
    int rb = blockIdx.x * 32;

    for (int t = tid; t < DH * DOUT / 4; t += 128)
        ((float4*)W2s)[t] = ((const float4*)W2)[t];
    for (int t = tid; t < 32 * 32; t += 128) {
        int r = t >> 5, q = t & 31;
        int row = rb + r;
        float4 v = make_float4(0.f, 0.f, 0.f, 0.f);
        if (row < M) v = ((const float4*)(g_out1 + (size_t)row * DH))[q];
        float* dst = &xs[r * 133 + q * 4];
        dst[0] = v.x; dst[1] = v.y; dst[2] = v.z; dst[3] = v.w;
    }
    __syncthreads();

    ull c0 = 0ull, c1 = 0ull;
#pragma unroll
    for (int k = 0; k < DH; k++) {
        float xv = xs[lane * 133 + k];
        ull xv2 = pk2(xv, xv);
        ulonglong2 wv = *((const ulonglong2*)&W2s[k * 8 + w * 2]);
        fma2(c0, xv2, wv.x);
        fma2(c1, xv2, wv.y);
    }

    int row = rb + lane;
    if (row < M) {
        ulonglong2 v; v.x = c0; v.y = c1;
        *((ulonglong2*)(g_h2 + (size_t)row * DOUT + w * 4)) = v;
    }
    ull asp0 = pk2(as[w * 4], as[w * 4 + 1]), asp1 = pk2(as[w * 4 + 2], as[w * 4 + 3]);
    ull adp0 = pk2(ad[w * 4], ad[w * 4 + 1]), adp1 = pk2(ad[w * 4 + 2], ad[w * 4 + 3]);
    ull ps2 = 0ull, pd2 = 0ull;
    fma2(ps2, c0, asp0); fma2(ps2, c1, asp1);
    fma2(pd2, c0, adp0); fma2(pd2, c1, adp1);
    float a, b, c, d;
    upk2(ps2, a, b); sred[0][lane][w] = a + b;
    upk2(pd2, c, d); sred[1][lane][w] = c + d;
    __syncthreads();
    if (tid < 64) {
        int r = tid & 31, which = tid >> 5;
        float sum = sred[which][r][0] + sred[which][r][1] + sred[which][r][2] + sred[which][r][3];
        int rr = rb + r;
        if (rr < M) {
            if (which == 0) g_als2[rr] = sum; else g_ald2[rr] = sum;
        }
    }
}

// ---------------------------------------------------------------------------
// agg2: TWO nodes per warp (16 lanes each), plain exp (no max)
__global__ void __launch_bounds__(256) k_agg2(const float* __restrict__ b2, int M) {
    int warp = (blockIdx.x * blockDim.x + threadIdx.x) >> 5;
    int lane = threadIdx.x & 31;
    int node = 2 * warp + (lane >> 4);
    int c = lane & 15;
    if (node >= M) return;
    int s = g_rowptr[node], e = g_rowptr[node + 1];
    float aldv = g_ald2[node];
    float ssum = 0.f, acc = 0.f;
#pragma unroll 4
    for (int i = s; i < e; i++) {
        int u = g_srcs[i];
        float logit = g_als2[u] + aldv;
        logit = (logit > 0.f) ? logit : 0.2f * logit;
        float p = __expf(logit);
        float hv = g_h2[(size_t)u * DOUT + c];
        ssum += p;
        acc += p * hv;
    }
    g_out2[(size_t)node * DOUT + c] = acc / ssum + b2[c];
}

// ---------------------------------------------------------------------------
// pool: strips of 64 sorted nodes; atomic flush only on graph-boundary change
__global__ void __launch_bounds__(256) k_pool(const int* __restrict__ batch, int M) {
    int tid = threadIdx.x;
    int strip = blockIdx.x * 16 + (tid >> 4);
    int c = tid & 15;
    int base = strip * 64;
    if (base >= M) return;
    float acc = 0.f, cacc = 0.f;
    int curg = -1;
    for (int t = 0; t < 64; t++) {
        int node = base + t;
        if (node >= M) break;
        int g = batch[node];
        if (g != curg) {
            if (curg >= 0) {
                atomicAdd(&g_pooled[curg * DOUT + c], acc);
                if (c == 0) atomicAdd(&g_cnt[curg], cacc);
            }
            curg = g; acc = 0.f; cacc = 0.f;
        }
        acc += g_out2[(size_t)node * DOUT + c];
        cacc += 1.f;
    }
    if (curg >= 0) {
        atomicAdd(&g_pooled[curg * DOUT + c], acc);
        if (c == 0) atomicAdd(&g_cnt[curg], cacc);
    }
}

// final: mean + log_softmax per graph; zero accumulators for next call
__global__ void k_final(float* __restrict__ out) {
    int g = threadIdx.x;
    if (g >= NG) return;
    float cnt = fmaxf(g_cnt[g], 1.f);
    float v[DOUT];
    float m = -1e30f;
#pragma unroll
    for (int c = 0; c < DOUT; c++) {
        v[c] = g_pooled[g * DOUT + c] / cnt;
        m = fmaxf(m, v[c]);
    }
    float s = 0.f;
#pragma unroll
    for (int c = 0; c < DOUT; c++) s += expf(v[c] - m);
    float lse = logf(s) + m;
#pragma unroll
    for (int c = 0; c < DOUT; c++) {
        out[g * DOUT + c] = v[c] - lse;
        g_pooled[g * DOUT + c] = 0.f;   // reset for next call
    }
    g_cnt[g] = 0.f;
}

// ---------------------------------------------------------------------------
extern "C" void kernel_launch(void* const* d_in, const int* in_sizes, int n_in,
                              void* d_out, int out_size) {
    const float* x   = (const float*)d_in[0];
    const int*   ei  = (const int*)d_in[1];
    const int*   bat = (const int*)d_in[2];
    const float* W1  = (const float*)d_in[3];
    const float* a1s = (const float*)d_in[4];
    const float* a1d = (const float*)d_in[5];
    const float* b1  = (const float*)d_in[6];
    const float* W2  = (const float*)d_in[7];
    const float* a2s = (const float*)d_in[8];
    const float* a2d = (const float*)d_in[9];
    const float* b2  = (const float*)d_in[10];

    int M = in_sizes[2];          // 50000 nodes
    int E = in_sizes[1] / 2;      // 640000 edges
    int E4 = E >> 2;

    static cudaStream_t s2 = nullptr;
    static cudaEvent_t evFork = nullptr, evJoin = nullptr;
    if (s2 == nullptr) {
        cudaStreamCreateWithFlags(&s2, cudaStreamNonBlocking);
        cudaEventCreateWithFlags(&evFork, cudaEventDisableTiming);
        cudaEventCreateWithFlags(&evJoin, cudaEventDisableTiming);
        cudaFuncSetAttribute(k_gemm1, cudaFuncAttributeMaxDynamicSharedMemorySize,
                             SMEM1_BYTES);
    }

    // fork: CSR build on s2, GEMM1 on the main stream
    cudaEventRecord(evFork, 0);
    cudaStreamWaitEvent(s2, evFork, 0);

    k_hist<<<(E4 + 1 + 255) / 256, 256, 0, s2>>>(ei, E);
    k_scan<<<1, 1024, 0, s2>>>(M);
    k_scatter<<<(E4 + 1 + M + 255) / 256, 256, 0, s2>>>(ei, E, M);
    cudaEventRecord(evJoin, s2);

    k_gemm1<<<(M + 63) / 64, 256, SMEM1_BYTES>>>(x, W1, a1s, a1d, M);

    // join before aggregation
    cudaStreamWaitEvent(0, evJoin, 0);

    k_agg1<<<(M + 7) / 8, 256>>>(b1, M);
    k_gemm2<<<(M + 31) / 32, 128>>>(W2, a2s, a2d, M);
    k_agg2<<<(M / 2 + 7) / 8, 256>>>(b2, M);
    k_pool<<<(M + 1023) / 1024, 256>>>(bat, M);
    k_final<<<1, 64>>>((float*)d_out);
}

// round 9
// speedup vs baseline: 1.4014x; 1.4014x over previous
#include <cuda_runtime.h>
#include <cuda_bf16.h>
#include <stdint.h>
#include <math.h>

#define NMAX 50000
#define EMAX 640000
#define ETOTMAX (EMAX + NMAX)
#define DH 128
#define DOUT 16
#define NG 64
#define WPITCH 136   // bf16 elements per row (272B) -> conflict-free ldmatrix

typedef unsigned long long ull;

// scratch (device globals; zero-initialized at module load)
__device__ float g_h1[NMAX * DH];
__device__ float g_out1[NMAX * DH];
__device__ float g_h2[NMAX * DOUT];
__device__ float g_out2[NMAX * DOUT];
__device__ float g_als1[NMAX], g_ald1[NMAX];
__device__ float g_als2[NMAX], g_ald2[NMAX];
__device__ int   g_deg[NMAX];          // zeroed by k_scatter for next call
__device__ int   g_rowptr[NMAX + 1];
__device__ int   g_cursor[NMAX];
__device__ int   g_srcs[ETOTMAX];
__device__ float g_pooled[NG * DOUT];  // zeroed by k_final for next call
__device__ float g_cnt[NG];
// W1 split-bf16, transposed [n][k] with pitch WPITCH: [hi | lo]
__device__ __nv_bfloat16 g_w1cv[2 * 128 * WPITCH];

// ---- packed fp32x2 helpers --------------------------------------------------
__device__ __forceinline__ ull pk2(float lo, float hi) {
    ull r; asm("mov.b64 %0, {%1, %2};" : "=l"(r) : "f"(lo), "f"(hi)); return r;
}
__device__ __forceinline__ void upk2(ull v, float& lo, float& hi) {
    asm("mov.b64 {%0, %1}, %2;" : "=f"(lo), "=f"(hi) : "l"(v));
}
__device__ __forceinline__ void fma2(ull& d, ull a, ull b) {
    asm("fma.rn.f32x2 %0, %1, %2, %3;" : "=l"(d) : "l"(a), "l"(b), "l"(d));
}

__device__ __forceinline__ uint32_t smem_u32(const void* p) {
    uint32_t a;
    asm("{ .reg .u64 t; cvta.to.shared.u64 t, %1; cvt.u32.u64 %0, t; }"
        : "=r"(a) : "l"(p));
    return a;
}

// ldmatrix x4 (non-transposed, b16)
#define LDSM_X4(r0, r1, r2, r3, addr) \
    asm volatile("ldmatrix.sync.aligned.m8n8.x4.shared.b16 {%0,%1,%2,%3}, [%4];" \
                 : "=r"(r0), "=r"(r1), "=r"(r2), "=r"(r3) : "r"(addr))

// mma m16n8k16 bf16 -> f32
#define MMA_BF16(c0, c1, c2, c3, a0, a1, a2, a3, b0, b1) \
    asm volatile("mma.sync.aligned.m16n8k16.row.col.f32.bf16.bf16.f32 " \
                 "{%0,%1,%2,%3}, {%4,%5,%6,%7}, {%8,%9}, {%0,%1,%2,%3};" \
                 : "+f"(c0), "+f"(c1), "+f"(c2), "+f"(c3) \
                 : "r"(a0), "r"(a1), "r"(a2), "r"(a3), "r"(b0), "r"(b1))

// ---------------------------------------------------------------------------
// W1 -> split bf16 transposed [n][k], pitch WPITCH
__global__ void k_wconv(const float* __restrict__ W) {
    int i = blockIdx.x * blockDim.x + threadIdx.x;
    if (i >= 16384) return;
    int k = i >> 7, n = i & 127;
    float v = W[i];                      // W[k][n]
    __nv_bfloat16 hi = __float2bfloat16(v);
    __nv_bfloat16 lo = __float2bfloat16(v - __bfloat162float(hi));
    g_w1cv[n * WPITCH + k] = hi;
    g_w1cv[128 * WPITCH + n * WPITCH + k] = lo;
}

// ---------------------------------------------------------------------------
// histogram of edge destination degrees (self loops handled algebraically)
__global__ void k_hist(const int* __restrict__ ei, int E) {
    int i = blockIdx.x * blockDim.x + threadIdx.x;
    int E4 = E >> 2;
    if (i < E4) {
        int4 d = ((const int4*)(ei + E))[i];
        atomicAdd(&g_deg[d.x], 1);
        atomicAdd(&g_deg[d.y], 1);
        atomicAdd(&g_deg[d.z], 1);
        atomicAdd(&g_deg[d.w], 1);
    } else if (i == E4) {
        for (int j = E4 * 4; j < E; j++) atomicAdd(&g_deg[ei[E + j]], 1);
    }
}

// single-block scan -> rowptr/cursor (prefix of deg+1)
__global__ void __launch_bounds__(1024) k_scan(int M) {
    __shared__ int warpsum[32];
    int t = threadIdx.x;
    int C = (M + 1023) >> 10;
    int lo = t * C, hi = min(lo + C, M);
    if (lo > M) lo = M;
    if (hi < lo) hi = lo;
    int s = 0;
    for (int i = lo; i < hi; i++) s += g_deg[i] + 1;
    int lane = t & 31, w = t >> 5;
    int v = s;
#pragma unroll
    for (int o = 1; o < 32; o <<= 1) {
        int u = __shfl_up_sync(0xffffffffu, v, o);
        if (lane >= o) v += u;
    }
    if (lane == 31) warpsum[w] = v;
    __syncthreads();
    if (w == 0) {
        int u = warpsum[lane];
#pragma unroll
        for (int o = 1; o < 32; o <<= 1) {
            int z = __shfl_up_sync(0xffffffffu, u, o);
            if (lane >= o) u += z;
        }
        warpsum[lane] = u;
    }
    __syncthreads();
    int excl = v - s + (w ? warpsum[w - 1] : 0);
    int run = excl;
    for (int i = lo; i < hi; i++) {
        g_rowptr[i] = run;
        g_cursor[i] = run;
        run += g_deg[i] + 1;
    }
    if (t == 1023) g_rowptr[M] = run;
}

// scatter srcs into CSR slots; self-loop threads also zero g_deg for next call
__global__ void k_scatter(const int* __restrict__ ei, int E, int M) {
    int i = blockIdx.x * blockDim.x + threadIdx.x;
    int E4 = E >> 2;
    if (i < E4) {
        int4 s4 = ((const int4*)ei)[i];
        int4 d4 = ((const int4*)(ei + E))[i];
        int p;
        p = atomicAdd(&g_cursor[d4.x], 1); g_srcs[p] = s4.x;
        p = atomicAdd(&g_cursor[d4.y], 1); g_srcs[p] = s4.y;
        p = atomicAdd(&g_cursor[d4.z], 1); g_srcs[p] = s4.z;
        p = atomicAdd(&g_cursor[d4.w], 1); g_srcs[p] = s4.w;
    } else if (i == E4) {
        for (int j = E4 * 4; j < E; j++) {
            int p = atomicAdd(&g_cursor[ei[E + j]], 1);
            g_srcs[p] = ei[j];
        }
    } else {
        int j = i - E4 - 1;
        if (j < M) {
            int p = atomicAdd(&g_cursor[j], 1);
            g_srcs[p] = j;
            g_deg[j] = 0;
        }
    }
}

// ---------------------------------------------------------------------------
// GEMM1 via mma.sync bf16 split (hi*hi + hi*lo + lo*hi), fp32 accumulate.
// 128-row tile / CTA, 8 warps, each warp computes 16 rows x 128 cols.
// Epilogue fuses h1 store + als1/ald1 dot products.
#define SMEMM_BYTES (4 * 128 * WPITCH * 2)   // Wh, Wl, Xh, Xl

extern "C" __global__ void __launch_bounds__(256) k_gemm1m(
    const float* __restrict__ x, const float* __restrict__ as_,
    const float* __restrict__ ad_, int M)
{
    extern __shared__ __nv_bfloat16 sm[];
    __nv_bfloat16* Wh = sm;
    __nv_bfloat16* Wl = Wh + 128 * WPITCH;
    __nv_bfloat16* Xh = Wl + 128 * WPITCH;
    __nv_bfloat16* Xl = Xh + 128 * WPITCH;

    int tid = threadIdx.x;
    int lane = tid & 31;
    int w = tid >> 5;
    int rb = blockIdx.x * 128;

    // stage W hi+lo (69632 B, int4 copies; g_w1cv rows have same pitch)
    for (int t = tid; t < 2 * 128 * WPITCH * 2 / 16; t += 256)
        ((int4*)Wh)[t] = ((const int4*)g_w1cv)[t];

    // convert x tile -> Xh/Xl (pitch WPITCH)
    for (int t = tid; t < 128 * 32; t += 256) {
        int r = t >> 5, q = t & 31;
        int row = rb + r;
        float4 v = make_float4(0.f, 0.f, 0.f, 0.f);
        if (row < M) v = ((const float4*)(x + (size_t)row * DH))[q];
        __nv_bfloat162 h01 = __floats2bfloat162_rn(v.x, v.y);
        __nv_bfloat162 h23 = __floats2bfloat162_rn(v.z, v.w);
        __nv_bfloat162 l01 = __floats2bfloat162_rn(
            v.x - __bfloat162float(h01.x), v.y - __bfloat162float(h01.y));
        __nv_bfloat162 l23 = __floats2bfloat162_rn(
            v.z - __bfloat162float(h23.x), v.w - __bfloat162float(h23.y));
        int o = r * WPITCH + q * 4;
        *(uint32_t*)&Xh[o]     = *(uint32_t*)&h01;
        *(uint32_t*)&Xh[o + 2] = *(uint32_t*)&h23;
        *(uint32_t*)&Xl[o]     = *(uint32_t*)&l01;
        *(uint32_t*)&Xl[o + 2] = *(uint32_t*)&l23;
    }
    __syncthreads();

    float c[16][4];
#pragma unroll
    for (int i = 0; i < 16; i++)
#pragma unroll
        for (int j = 0; j < 4; j++) c[i][j] = 0.f;

    int mrow = w * 16;
    // per-lane ldmatrix row offsets
    int aRow = mrow + (lane & 15);
    int aKo  = (lane >> 4) * 8;
    int bRow = (lane & 7) + ((lane >> 4) << 3);
    int bKo  = ((lane >> 3) & 1) * 8;

#pragma unroll
    for (int ks = 0; ks < 8; ks++) {
        int k0 = ks * 16;
        uint32_t ah0, ah1, ah2, ah3, al0, al1, al2, al3;
        {
            uint32_t addrH = smem_u32(&Xh[aRow * WPITCH + k0 + aKo]);
            uint32_t addrL = smem_u32(&Xl[aRow * WPITCH + k0 + aKo]);
            LDSM_X4(ah0, ah1, ah2, ah3, addrH);
            LDSM_X4(al0, al1, al2, al3, addrL);
        }
#pragma unroll
        for (int np = 0; np < 8; np++) {
            int n0 = np * 16;
            uint32_t bh0, bh1, bh2, bh3, bl0, bl1, bl2, bl3;
            uint32_t addrH = smem_u32(&Wh[(n0 + bRow) * WPITCH + k0 + bKo]);
            uint32_t addrL = smem_u32(&Wl[(n0 + bRow) * WPITCH + k0 + bKo]);
            LDSM_X4(bh0, bh1, bh2, bh3, addrH);
            LDSM_X4(bl0, bl1, bl2, bl3, addrL);
            int t0 = np * 2, t1 = np * 2 + 1;
            // hi * hi
            MMA_BF16(c[t0][0], c[t0][1], c[t0][2], c[t0][3],
                     ah0, ah1, ah2, ah3, bh0, bh1);
            MMA_BF16(c[t1][0], c[t1][1], c[t1][2], c[t1][3],
                     ah0, ah1, ah2, ah3, bh2, bh3);
            // hi(A) * lo(B)
            MMA_BF16(c[t0][0], c[t0][1], c[t0][2], c[t0][3],
                     ah0, ah1, ah2, ah3, bl0, bl1);
            MMA_BF16(c[t1][0], c[t1][1], c[t1][2], c[t1][3],
                     ah0, ah1, ah2, ah3, bl2, bl3);
            // lo(A) * hi(B)
            MMA_BF16(c[t0][0], c[t0][1], c[t0][2], c[t0][3],
                     al0, al1, al2, al3, bh0, bh1);
            MMA_BF16(c[t1][0], c[t1][1], c[t1][2], c[t1][3],
                     al0, al1, al2, al3, bh2, bh3);
        }
    }

    // epilogue: store h1 + fused als/ald partial dots
    int colb = (lane & 3) * 2;
    int row0 = rb + mrow + (lane >> 2);
    int row1 = row0 + 8;
    float als0 = 0.f, ald0 = 0.f, als1 = 0.f, ald1 = 0.f;
#pragma unroll
    for (int nt = 0; nt < 16; nt++) {
        int c0i = nt * 8 + colb;
        float a0 = as_[c0i], a1 = as_[c0i + 1];
        float d0 = ad_[c0i], d1 = ad_[c0i + 1];
        als0 += c[nt][0] * a0 + c[nt][1] * a1;
        ald0 += c[nt][0] * d0 + c[nt][1] * d1;
        als1 += c[nt][2] * a0 + c[nt][3] * a1;
        ald1 += c[nt][2] * d0 + c[nt][3] * d1;
        if (row0 < M)
            *(float2*)(g_h1 + (size_t)row0 * DH + c0i) = make_float2(c[nt][0], c[nt][1]);
        if (row1 < M)
            *(float2*)(g_h1 + (size_t)row1 * DH + c0i) = make_float2(c[nt][2], c[nt][3]);
    }
    // reduce across the 4 lanes of each quad (same row)
    als0 += __shfl_xor_sync(0xffffffffu, als0, 1);
    als0 += __shfl_xor_sync(0xffffffffu, als0, 2);
    ald0 += __shfl_xor_sync(0xffffffffu, ald0, 1);
    ald0 += __shfl_xor_sync(0xffffffffu, ald0, 2);
    als1 += __shfl_xor_sync(0xffffffffu, als1, 1);
    als1 += __shfl_xor_sync(0xffffffffu, als1, 2);
    ald1 += __shfl_xor_sync(0xffffffffu, ald1, 1);
    ald1 += __shfl_xor_sync(0xffffffffu, ald1, 2);
    if ((lane & 3) == 0) {
        if (row0 < M) { g_als1[row0] = als0; g_ald1[row0] = ald0; }
        if (row1 < M) { g_als1[row1] = als1; g_ald1[row1] = ald1; }
    }
}

// ---------------------------------------------------------------------------
// agg1: one warp per dst node; bounded logits -> plain exp, unrolled gather
__global__ void __launch_bounds__(256) k_agg1(const float* __restrict__ b1, int M) {
    int warp = (blockIdx.x * blockDim.x + threadIdx.x) >> 5;
    int lane = threadIdx.x & 31;
    if (warp >= M) return;
    int s = g_rowptr[warp], e = g_rowptr[warp + 1];
    float aldv = g_ald1[warp];
    float ssum = 0.f;
    float4 acc = make_float4(0.f, 0.f, 0.f, 0.f);
#pragma unroll 4
    for (int i = s; i < e; i++) {
        int u = g_srcs[i];
        float logit = g_als1[u] + aldv;
        logit = (logit > 0.f) ? logit : 0.2f * logit;
        float p = __expf(logit);
        const float4 hv = ((const float4*)(g_h1 + (size_t)u * DH))[lane];
        ssum += p;
        acc.x += p * hv.x;
        acc.y += p * hv.y;
        acc.z += p * hv.z;
        acc.w += p * hv.w;
    }
    float inv = 1.f / ssum;
    float4 bv = ((const float4*)b1)[lane];
    float4 o;
    o.x = fmaxf(acc.x * inv + bv.x, 0.f);
    o.y = fmaxf(acc.y * inv + bv.y, 0.f);
    o.z = fmaxf(acc.z * inv + bv.z, 0.f);
    o.w = fmaxf(acc.w * inv + bv.w, 0.f);
    ((float4*)(g_out1 + (size_t)warp * DH))[lane] = o;
}

// ---------------------------------------------------------------------------
// GEMM2: h2[M,16] = out1 @ W2, packed f32x2. 128 threads / 32-row tile.
__global__ void __launch_bounds__(128) k_gemm2(
    const float* __restrict__ W2, const float* __restrict__ as,
    const float* __restrict__ ad, int M)
{
    __shared__ ull   W2s[DH * 8];        // [k][8 pairs]
    __shared__ float xs[32 * 133];       // [r][k], pitch 133
    __shared__ float sred[2][32][4];

    int tid = threadIdx.x;
    int lane = tid & 31;
    int w = tid >> 5;
    int rb = blockIdx.x * 32;

    for (int t = tid; t < DH * DOUT / 4; t += 128)
        ((float4*)W2s)[t] = ((const float4*)W2)[t];
    for (int t = tid; t < 32 * 32; t += 128) {
        int r = t >> 5, q = t & 31;
        int row = rb + r;
        float4 v = make_float4(0.f, 0.f, 0.f, 0.f);
        if (row < M) v = ((const float4*)(g_out1 + (size_t)row * DH))[q];
        float* dst = &xs[r * 133 + q * 4];
        dst[0] = v.x; dst[1] = v.y; dst[2] = v.z; dst[3] = v.w;
    }
    __syncthreads();

    ull c0 = 0ull, c1 = 0ull;
#pragma unroll
    for (int k = 0; k < DH; k++) {
        float xv = xs[lane * 133 + k];
        ull xv2 = pk2(xv, xv);
        ulonglong2 wv = *((const ulonglong2*)&W2s[k * 8 + w * 2]);
        fma2(c0, xv2, wv.x);
        fma2(c1, xv2, wv.y);
    }

    int row = rb + lane;
    if (row < M) {
        ulonglong2 v; v.x = c0; v.y = c1;
        *((ulonglong2*)(g_h2 + (size_t)row * DOUT + w * 4)) = v;
    }
    ull asp0 = pk2(as[w * 4], as[w * 4 + 1]), asp1 = pk2(as[w * 4 + 2], as[w * 4 + 3]);
    ull adp0 = pk2(ad[w * 4], ad[w * 4 + 1]), adp1 = pk2(ad[w * 4 + 2], ad[w * 4 + 3]);
    ull ps2 = 0ull, pd2 = 0ull;
    fma2(ps2, c0, asp0); fma2(ps2, c1, asp1);
    fma2(pd2, c0, adp0); fma2(pd2, c1, adp1);
    float a, b, c, d;
    upk2(ps2, a, b); sred[0][lane][w] = a + b;
    upk2(pd2, c, d); sred[1][lane][w] = c + d;
    __syncthreads();
    if (tid < 64) {
        int r = tid & 31, which = tid >> 5;
        float sum = sred[which][r][0] + sred[which][r][1] + sred[which][r][2] + sred[which][r][3];
        int rr = rb + r;
        if (rr < M) {
            if (which == 0) g_als2[rr] = sum; else g_ald2[rr] = sum;
        }
    }
}

// ---------------------------------------------------------------------------
// agg2: TWO nodes per warp (16 lanes each), plain exp (no max)
__global__ void __launch_bounds__(256) k_agg2(const float* __restrict__ b2, int M) {
    int warp = (blockIdx.x * blockDim.x + threadIdx.x) >> 5;
    int lane = threadIdx.x & 31;
    int node = 2 * warp + (lane >> 4);
    int c = lane & 15;
    if (node >= M) return;
    int s = g_rowptr[node], e = g_rowptr[node + 1];
    float aldv = g_ald2[node];
    float ssum = 0.f, acc = 0.f;
#pragma unroll 4
    for (int i = s; i < e; i++) {
        int u = g_srcs[i];
        float logit = g_als2[u] + aldv;
        logit = (logit > 0.f) ? logit : 0.2f * logit;
        float p = __expf(logit);
        float hv = g_h2[(size_t)u * DOUT + c];
        ssum += p;
        acc += p * hv;
    }
    g_out2[(size_t)node * DOUT + c] = acc / ssum + b2[c];
}

// ---------------------------------------------------------------------------
// pool: strips of 64 sorted nodes; atomic flush only on graph-boundary change
__global__ void __launch_bounds__(256) k_pool(const int* __restrict__ batch, int M) {
    int tid = threadIdx.x;
    int strip = blockIdx.x * 16 + (tid >> 4);
    int c = tid & 15;
    int base = strip * 64;
    if (base >= M) return;
    float acc = 0.f, cacc = 0.f;
    int curg = -1;
    for (int t = 0; t < 64; t++) {
        int node = base + t;
        if (node >= M) break;
        int g = batch[node];
        if (g != curg) {
            if (curg >= 0) {
                atomicAdd(&g_pooled[curg * DOUT + c], acc);
                if (c == 0) atomicAdd(&g_cnt[curg], cacc);
            }
            curg = g; acc = 0.f; cacc = 0.f;
        }
        acc += g_out2[(size_t)node * DOUT + c];
        cacc += 1.f;
    }
    if (curg >= 0) {
        atomicAdd(&g_pooled[curg * DOUT + c], acc);
        if (c == 0) atomicAdd(&g_cnt[curg], cacc);
    }
}

// final: mean + log_softmax per graph; zero accumulators for next call
__global__ void k_final(float* __restrict__ out) {
    int g = threadIdx.x;
    if (g >= NG) return;
    float cnt = fmaxf(g_cnt[g], 1.f);
    float v[DOUT];
    float m = -1e30f;
#pragma unroll
    for (int c = 0; c < DOUT; c++) {
        v[c] = g_pooled[g * DOUT + c] / cnt;
        m = fmaxf(m, v[c]);
    }
    float s = 0.f;
#pragma unroll
    for (int c = 0; c < DOUT; c++) s += expf(v[c] - m);
    float lse = logf(s) + m;
#pragma unroll
    for (int c = 0; c < DOUT; c++) {
        out[g * DOUT + c] = v[c] - lse;
        g_pooled[g * DOUT + c] = 0.f;
    }
    g_cnt[g] = 0.f;
}

// ---------------------------------------------------------------------------
extern "C" void kernel_launch(void* const* d_in, const int* in_sizes, int n_in,
                              void* d_out, int out_size) {
    const float* x   = (const float*)d_in[0];
    const int*   ei  = (const int*)d_in[1];
    const int*   bat = (const int*)d_in[2];
    const float* W1  = (const float*)d_in[3];
    const float* a1s = (const float*)d_in[4];
    const float* a1d = (const float*)d_in[5];
    const float* b1  = (const float*)d_in[6];
    const float* W2  = (const float*)d_in[7];
    const float* a2s = (const float*)d_in[8];
    const float* a2d = (const float*)d_in[9];
    const float* b2  = (const float*)d_in[10];

    int M = in_sizes[2];          // 50000 nodes
    int E = in_sizes[1] / 2;      // 640000 edges
    int E4 = E >> 2;

    static cudaStream_t s2 = nullptr;
    static cudaEvent_t evFork = nullptr, evJoin = nullptr;
    if (s2 == nullptr) {
        cudaStreamCreateWithFlags(&s2, cudaStreamNonBlocking);
        cudaEventCreateWithFlags(&evFork, cudaEventDisableTiming);
        cudaEventCreateWithFlags(&evJoin, cudaEventDisableTiming);
        cudaFuncSetAttribute(k_gemm1m, cudaFuncAttributeMaxDynamicSharedMemorySize,
                             SMEMM_BYTES);
    }

    // fork: CSR build on s2; W convert + GEMM1 on main stream
    cudaEventRecord(evFork, 0);
    cudaStreamWaitEvent(s2, evFork, 0);

    k_hist<<<(E4 + 1 + 255) / 256, 256, 0, s2>>>(ei, E);
    k_scan<<<1, 1024, 0, s2>>>(M);
    k_scatter<<<(E4 + 1 + M + 255) / 256, 256, 0, s2>>>(ei, E, M);
    cudaEventRecord(evJoin, s2);

    k_wconv<<<64, 256>>>(W1);
    k_gemm1m<<<(M + 127) / 128, 256, SMEMM_BYTES>>>(x, a1s, a1d, M);

    cudaStreamWaitEvent(0, evJoin, 0);

    k_agg1<<<(M + 7) / 8, 256>>>(b1, M);
    k_gemm2<<<(M + 31) / 32, 128>>>(W2, a2s, a2d, M);
    k_agg2<<<(M / 2 + 7) / 8, 256>>>(b2, M);
    k_pool<<<(M + 1023) / 1024, 256>>>(bat, M);
    k_final<<<1, 64>>>((float*)d_out);
}